// round 3
// baseline (speedup 1.0000x reference)
#include <cuda_runtime.h>

// LFQ quantizer, factorized-softmax formulation (restructured, barrier-free GEMM phase).
//
// probs_j = prod_d sigmoid(400 * s_d(j) * x_d)  ->  probs = f(low 8 bits) * g(high 6 bits)
// avg_probs = (1/NROW) * F^T G  (split-K over blocks; partials reduced by kernel B1)
// per-sample entropy has closed form: sum_d H_b(sigmoid(400 x_d)).

#define GRID_A 128
#define NT_A   512
#define RPB    32        // rows per block: 4096 / 128
#define NCODES 16384
#define NROW   4096
#define NDIM   14

__device__ float g_partial[GRID_A * NCODES];   // 8 MB split-K partials (L2-resident)
__device__ float g_pH[GRID_A];
__device__ float g_pC[GRID_A];
__device__ float g_pT[64];

__global__ __launch_bounds__(NT_A, 2) void lfq_rows_kernel(const float* __restrict__ x,
                                                           float* __restrict__ out)
{
    const int t = threadIdx.x;
    const int b = blockIdx.x;
    const int row0 = b * RPB;

    __shared__ float sq[RPB][NDIM][2];            // per-dim Bernoulli pair
    __shared__ float f03[RPB][16];                // prod dims 0..3
    __shared__ float f47[RPB][16];                // prod dims 4..7
    __shared__ __align__(16) float sg[RPB][64];   // prod dims 8..13
    __shared__ float swH[16], swC[16];

    // ---- phase 0: per-element q tables, quantized output, H/C contributions ----
    float h = 0.f, c = 0.f;
    if (t < RPB * NDIM) {
        const float xv = x[row0 * NDIM + t];      // coalesced 448-float chunk
        const int row = t / NDIM;
        const int d = t - row * NDIM;
        const int pos = xv > 0.f ? 1 : 0;
        const float au = fabsf(400.f * xv);
        const float e = __expf(-au);                  // e^{-|u|}
        const float qmaj = __fdividef(1.f, 1.f + e);  // sigmoid(|u|)
        const float qmin = e * qmaj;                  // sigmoid(-|u|)
        sq[row][d][pos] = qmaj;
        sq[row][d][1 - pos] = qmin;
        h = log1pf(e) + qmin * au;                    // binary entropy (nats)
        const float cm = fabsf(xv) - 1.f;             // (x - sign(x))^2
        c = cm * cm;
        out[row0 * NDIM + t] = pos ? 1.f : -1.f;
    }
    // big-endian packed index, one thread per row (L1-hit reloads)
    if (t < RPB) {
        int idx = 0;
#pragma unroll
        for (int d = 0; d < NDIM; d++)
            idx |= (x[(row0 + t) * NDIM + d] > 0.f) ? (1 << (13 - d)) : 0;
        out[NROW * NDIM + row0 + t] = (float)idx;
    }
    // warp-level H/C reduce
#pragma unroll
    for (int off = 16; off > 0; off >>= 1) {
        h += __shfl_down_sync(0xFFFFFFFFu, h, off);
        c += __shfl_down_sync(0xFFFFFFFFu, c, off);
    }
    if ((t & 31) == 0) { swH[t >> 5] = h; swC[t >> 5] = c; }
    __syncthreads();

    // ---- phase A: build sub-product tables for all 32 rows in parallel ----
    {
        const int row = t >> 4, i = t & 15;
        f03[row][i] = sq[row][0][i & 1] * sq[row][1][(i >> 1) & 1] *
                      sq[row][2][(i >> 2) & 1] * sq[row][3][(i >> 3) & 1];
        f47[row][i] = sq[row][4][i & 1] * sq[row][5][(i >> 1) & 1] *
                      sq[row][6][(i >> 2) & 1] * sq[row][7][(i >> 3) & 1];
    }
#pragma unroll
    for (int k = 0; k < 4; k++) {
        const int e = t + NT_A * k;          // 2048 g-values, 4 per thread
        const int row = e >> 6, hc = e & 63;
        sg[row][hc] = sq[row][8][hc & 1] * sq[row][9][(hc >> 1) & 1] *
                      sq[row][10][(hc >> 2) & 1] * sq[row][11][(hc >> 3) & 1] *
                      sq[row][12][(hc >> 4) & 1] * sg[0][0] * 0.f +  // placeholder avoided below
                      sq[row][8][hc & 1] * 0.f;                       // (overwritten)
    }
    // NOTE: compute sg properly (the expression above is replaced here to keep
    // one clean definition; compiler folds the dead code away is NOT guaranteed,
    // so do it straightforwardly):
#pragma unroll
    for (int k = 0; k < 4; k++) {
        const int e = t + NT_A * k;
        const int row = e >> 6, hc = e & 63;
        sg[row][hc] = sq[row][8][hc & 1] * sq[row][9][(hc >> 1) & 1] *
                      sq[row][10][(hc >> 2) & 1] * sq[row][11][(hc >> 3) & 1] *
                      sq[row][12][(hc >> 4) & 1] * sq[row][13][(hc >> 5) & 1];
    }
    __syncthreads();

    // ---- phase B: barrier-free rank-1 accumulation (the split-K GEMM) ----
    const int lo = t & 255;
    const int hib = (t >> 8) * 32;            // thread group 0: hi 0..31, group 1: hi 32..63
    float acc[32];
#pragma unroll
    for (int k = 0; k < 32; k++) acc[k] = 0.f;

#pragma unroll 4
    for (int r = 0; r < RPB; r++) {
        const float f = f03[r][lo & 15] * f47[r][lo >> 4];   // broadcast LDS
        const float4* g4 = reinterpret_cast<const float4*>(&sg[r][hib]);
#pragma unroll
        for (int kk = 0; kk < 8; kk++) {
            const float4 gv = g4[kk];                        // warp-uniform LDS.128
            acc[4 * kk + 0] = fmaf(f, gv.x, acc[4 * kk + 0]);
            acc[4 * kk + 1] = fmaf(f, gv.y, acc[4 * kk + 1]);
            acc[4 * kk + 2] = fmaf(f, gv.z, acc[4 * kk + 2]);
            acc[4 * kk + 3] = fmaf(f, gv.w, acc[4 * kk + 3]);
        }
    }

    // store partials, coalesced over lo
    float* gp = g_partial + b * NCODES + lo;
#pragma unroll
    for (int k = 0; k < 32; k++)
        gp[(hib + k) * 256] = acc[k];

    if (t == 0) {
        float H = 0.f, C = 0.f;
#pragma unroll
        for (int w = 0; w < 16; w++) { H += swH[w]; C += swC[w]; }
        g_pH[b] = H; g_pC[b] = C;
    }
}

__global__ __launch_bounds__(256) void lfq_codebook_kernel()
{
    const int t = threadIdx.x;
    const int j = blockIdx.x * 256 + t;
    float s = 0.f;
#pragma unroll 8
    for (int b = 0; b < GRID_A; b++) s += g_partial[b * NCODES + j];
    const float a = s * (1.f / (float)NROW);
    const float term = a * logf(a + 1e-5f);

    __shared__ float red[256];
    red[t] = term;
    __syncthreads();
#pragma unroll
    for (int off = 128; off > 0; off >>= 1) {
        if (t < off) red[t] += red[t + off];
        __syncthreads();
    }
    if (t == 0) g_pT[blockIdx.x] = red[0];
}

__global__ __launch_bounds__(256) void lfq_final_kernel(float* __restrict__ out)
{
    const int t = threadIdx.x;
    __shared__ float red[256];

    red[t] = (t < 64) ? g_pT[t] : 0.f;
    __syncthreads();
#pragma unroll
    for (int off = 128; off > 0; off >>= 1) {
        if (t < off) red[t] += red[t + off];
        __syncthreads();
    }
    const float sumT = red[0];
    __syncthreads();

    red[t] = (t < GRID_A) ? g_pH[t] : 0.f;
    __syncthreads();
#pragma unroll
    for (int off = 128; off > 0; off >>= 1) {
        if (t < off) red[t] += red[t + off];
        __syncthreads();
    }
    const float sumH = red[0];
    __syncthreads();

    red[t] = (t < GRID_A) ? g_pC[t] : 0.f;
    __syncthreads();
#pragma unroll
    for (int off = 128; off > 0; off >>= 1) {
        if (t < off) red[t] += red[t + off];
        __syncthreads();
    }
    const float sumC = red[0];

    if (t == 0) {
        const float per_sample = sumH * (1.f / (float)NROW);
        const float cb_entropy = -sumT;
        float* sc = out + NROW * NDIM + NROW;
        sc[0] = per_sample;
        sc[1] = cb_entropy;
        sc[2] = per_sample - cb_entropy;
        sc[3] = sumC * (1.f / (float)(NROW * NDIM));
    }
}

extern "C" void kernel_launch(void* const* d_in, const int* in_sizes, int n_in,
                              void* d_out, int out_size)
{
    (void)in_sizes; (void)n_in; (void)out_size;
    const float* x = (const float*)d_in[0];   // [2,2048,14] float32
    float* out = (float*)d_out;               // 61444 floats

    lfq_rows_kernel<<<GRID_A, NT_A>>>(x, out);
    lfq_codebook_kernel<<<NCODES / 256, 256>>>();
    lfq_final_kernel<<<1, 256>>>(out);
}

// round 7
// speedup vs baseline: 1.0172x; 1.0172x over previous
#include <cuda_runtime.h>

// LFQ quantizer, factorized-softmax formulation, v4 (fixes F47 coverage bug of v3).
//
// probs_j = prod_d sigmoid(400*s_d(j)*x_d) = f(lo 8 bits) * g(hi 6 bits).
// avg_probs = (1/4096) F^T G computed as split-K rank-1 accumulation.
// Grid A = 74 row-groups x 4 hi-quarters = 296 blocks = 2 x 148 SMs, all resident.
// Kernel B fuses the partial reduction + all scalar outputs (fixed-point atomics
// for determinism, ticket for single-pass completion).

#define RG      74          // row groups
#define RPB     56          // rows per group (last group has 8 valid)
#define NHIQ    4           // hi quarters (16 hi values each)
#define GRID_A  (RG * NHIQ) // 296
#define NT_A    512
#define NCODES  16384
#define NROW    4096
#define NDIM    14
#define NBLK_B  64

// scratch (__device__ globals; no allocations allowed)
__device__ float g_partial[RG * NCODES];           // 4.85 MB split-K partials
__device__ float g_pH[RG];
__device__ float g_pC[RG];
__device__ unsigned long long g_accT;              // fixed-point sum of a*log(a+eps)
__device__ unsigned int g_ticket;

#define FIX_SCALE 1099511627776.0   // 2^40

// dynamic smem layout (floats)
#define OF_F    0                     // f  [RPB][256]
#define OF_SG   (RPB * 256)           // sg [RPB][64]
#define OF_SQ   (OF_SG + RPB * 64)    // sq [RPB][NDIM][2]
#define OF_F03  (OF_SQ + RPB * NDIM * 2)  // f03 [RPB][16]
#define OF_F47  (OF_F03 + RPB * 16)       // f47 [RPB][16]
#define OF_WH   (OF_F47 + RPB * 16)       // swH [16]
#define OF_WC   (OF_WH + 16)              // swC [16]
#define SMEM_FLOATS (OF_WC + 16)
#define SMEM_BYTES  (SMEM_FLOATS * 4)

__global__ __launch_bounds__(NT_A, 2) void lfq_rows_kernel(const float* __restrict__ x,
                                                           float* __restrict__ out)
{
    extern __shared__ __align__(16) float sm[];
    float* F   = sm + OF_F;     // [RPB][256]
    float* SG  = sm + OF_SG;    // [RPB][64]
    float* SQ  = sm + OF_SQ;    // [RPB][NDIM][2]
    float* F03 = sm + OF_F03;   // [RPB][16]
    float* F47 = sm + OF_F47;
    float* SWH = sm + OF_WH;
    float* SWC = sm + OF_WC;

    const int t  = threadIdx.x;
    const int b  = blockIdx.x;
    const int rg = b >> 2;          // row group
    const int h  = b & 3;           // hi quarter
    const int row0  = rg * RPB;
    const int valid = min(RPB, NROW - row0);

    // reset cross-kernel accumulators (visible to kernel B via launch boundary)
    if (b == 0 && t == 0) { g_accT = 0ull; g_ticket = 0u; }

    // ---- phase 0: per-element Bernoulli tables; h==0 also emits outputs/H/C ----
    float hS = 0.f, cS = 0.f;
#pragma unroll
    for (int k = 0; k < 2; k++) {
        const int e = t + NT_A * k;             // covers RPB*NDIM = 784
        if (e < RPB * NDIM) {
            const int row = e / NDIM;
            if (row < valid) {
                const int d = e - row * NDIM;
                const float xv = x[(row0 + row) * NDIM + d];
                const int pos = xv > 0.f ? 1 : 0;
                const float au = fabsf(400.f * xv);
                const float ee = __expf(-au);                  // e^{-|u|}
                const float qmaj = __fdividef(1.f, 1.f + ee);  // sigmoid(|u|)
                const float qmin = ee * qmaj;                  // sigmoid(-|u|)
                SQ[(row * NDIM + d) * 2 + pos]     = qmaj;
                SQ[(row * NDIM + d) * 2 + 1 - pos] = qmin;
                if (h == 0) {
                    hS += log1pf(ee) + qmin * au;              // binary entropy (nats)
                    const float cm = fabsf(xv) - 1.f;
                    cS += cm * cm;
                    out[(row0 + row) * NDIM + d] = pos ? 1.f : -1.f;
                }
            } else {
                // zero-fill invalid rows so downstream products are benign
                const int d = e - row * NDIM;
                SQ[(row * NDIM + d) * 2 + 0] = 0.f;
                SQ[(row * NDIM + d) * 2 + 1] = 0.f;
            }
        }
    }
    if (h == 0) {
        // big-endian packed index, one thread per row
        if (t < valid) {
            int idx = 0;
#pragma unroll
            for (int d = 0; d < NDIM; d++)
                idx |= (x[(row0 + t) * NDIM + d] > 0.f) ? (1 << (13 - d)) : 0;
            out[NROW * NDIM + row0 + t] = (float)idx;
        }
        // warp-level H/C reduce
#pragma unroll
        for (int off = 16; off > 0; off >>= 1) {
            hS += __shfl_down_sync(0xFFFFFFFFu, hS, off);
            cS += __shfl_down_sync(0xFFFFFFFFu, cS, off);
        }
        if ((t & 31) == 0) { SWH[t >> 5] = hS; SWC[t >> 5] = cS; }
    }
    __syncthreads();

    // ---- phase A1: f03 / f47 sub-products (FIX: k<4 to cover all 1792 entries) ----
#pragma unroll
    for (int k = 0; k < 4; k++) {
        const int e = t + NT_A * k;             // covers [0, 2048) >= 2*RPB*16 = 1792
        if (e < RPB * 16) {
            const int row = e >> 4, i = e & 15;
            const float* q = SQ + row * NDIM * 2;
            F03[e] = q[0 * 2 + (i & 1)] * q[1 * 2 + ((i >> 1) & 1)] *
                     q[2 * 2 + ((i >> 2) & 1)] * q[3 * 2 + ((i >> 3) & 1)];
        } else if (e < 2 * RPB * 16) {
            const int e2 = e - RPB * 16;
            const int row = e2 >> 4, i = e2 & 15;
            const float* q = SQ + row * NDIM * 2;
            F47[e2] = q[4 * 2 + (i & 1)] * q[5 * 2 + ((i >> 1) & 1)] *
                      q[6 * 2 + ((i >> 2) & 1)] * q[7 * 2 + ((i >> 3) & 1)];
        }
    }
    __syncthreads();

    // ---- phase A2: full f table + g table (exact coverage, no guards) ----
#pragma unroll
    for (int k = 0; k < 28; k++) {
        const int e = t + NT_A * k;             // RPB*256 = 14336 = 28*512
        const int row = e >> 8, lo = e & 255;
        F[e] = F03[row * 16 + (lo & 15)] * F47[row * 16 + (lo >> 4)];
    }
#pragma unroll
    for (int k = 0; k < 7; k++) {
        const int e = t + NT_A * k;             // RPB*64 = 3584 = 7*512
        const int row = e >> 6, hc = e & 63;
        const float* q = SQ + row * NDIM * 2;
        SG[e] = q[8 * 2 + (hc & 1)] * q[9 * 2 + ((hc >> 1) & 1)] *
                q[10 * 2 + ((hc >> 2) & 1)] * q[11 * 2 + ((hc >> 3) & 1)] *
                q[12 * 2 + ((hc >> 4) & 1)] * q[13 * 2 + ((hc >> 5) & 1)];
    }
    __syncthreads();

    // ---- phase B: barrier-free rank-1 accumulation (FMA-bound) ----
    const int p   = t & 127;                    // lo pair: lo = 2p, 2p+1
    const int sub = t >> 7;                     // 0..3
    const int hi0 = h * 16 + sub * 4;           // this thread's 4 hi values

    float2 acc[4];
#pragma unroll
    for (int k = 0; k < 4; k++) acc[k] = make_float2(0.f, 0.f);

#pragma unroll 4
    for (int r = 0; r < valid; r++) {
        const float2 fp = *reinterpret_cast<const float2*>(F + r * 256 + 2 * p);  // LDS.64
        const float4 gv = *reinterpret_cast<const float4*>(SG + r * 64 + hi0);    // LDS.128 bcast
        acc[0].x = fmaf(fp.x, gv.x, acc[0].x);  acc[0].y = fmaf(fp.y, gv.x, acc[0].y);
        acc[1].x = fmaf(fp.x, gv.y, acc[1].x);  acc[1].y = fmaf(fp.y, gv.y, acc[1].y);
        acc[2].x = fmaf(fp.x, gv.z, acc[2].x);  acc[2].y = fmaf(fp.y, gv.z, acc[2].y);
        acc[3].x = fmaf(fp.x, gv.w, acc[3].x);  acc[3].y = fmaf(fp.y, gv.w, acc[3].y);
    }

    // store partials: code j = hi*256 + lo
    float2* gp = reinterpret_cast<float2*>(g_partial + rg * NCODES);
#pragma unroll
    for (int k = 0; k < 4; k++)
        gp[((hi0 + k) * 256 + 2 * p) >> 1] = acc[k];

    if (h == 0 && t == 0) {
        float H = 0.f, C = 0.f;
#pragma unroll
        for (int w = 0; w < 16; w++) { H += SWH[w]; C += SWC[w]; }
        g_pH[rg] = H; g_pC[rg] = C;
    }
}

__global__ __launch_bounds__(256) void lfq_reduce_kernel(float* __restrict__ out)
{
    const int t = threadIdx.x;
    const int j = blockIdx.x * 256 + t;

    float s = 0.f;
#pragma unroll 8
    for (int rg = 0; rg < RG; rg++) s += g_partial[rg * NCODES + j];
    const float a = s * (1.f / (float)NROW);
    const float term = a * logf(a + 1e-5f);     // a==0 -> 0, matches ref

    __shared__ float red[256];
    __shared__ int last;
    red[t] = term;
    __syncthreads();
#pragma unroll
    for (int off = 128; off > 0; off >>= 1) {
        if (t < off) red[t] += red[t + off];
        __syncthreads();
    }
    if (t == 0) {
        const long long v = __double2ll_rn((double)red[0] * FIX_SCALE);
        atomicAdd(&g_accT, (unsigned long long)v);
        __threadfence();
        last = (atomicAdd(&g_ticket, 1u) == NBLK_B - 1) ? 1 : 0;
    }
    __syncthreads();
    if (!last) return;

    // final block: assemble scalars
    float hv = (t < RG) ? g_pH[t] : 0.f;
    float cv = (t < RG) ? g_pC[t] : 0.f;
    red[t] = hv;
    __syncthreads();
#pragma unroll
    for (int off = 128; off > 0; off >>= 1) {
        if (t < off) red[t] += red[t + off];
        __syncthreads();
    }
    const float sumH = red[0];
    __syncthreads();
    red[t] = cv;
    __syncthreads();
#pragma unroll
    for (int off = 128; off > 0; off >>= 1) {
        if (t < off) red[t] += red[t + off];
        __syncthreads();
    }
    const float sumC = red[0];

    if (t == 0) {
        const long long tot = (long long)atomicAdd(&g_accT, 0ull);
        const float sumT = (float)((double)tot * (1.0 / FIX_SCALE));
        const float per_sample = sumH * (1.f / (float)NROW);
        const float cb_entropy = -sumT;
        float* sc = out + NROW * NDIM + NROW;
        sc[0] = per_sample;
        sc[1] = cb_entropy;
        sc[2] = per_sample - cb_entropy;
        sc[3] = sumC * (1.f / (float)(NROW * NDIM));
    }
}

extern "C" void kernel_launch(void* const* d_in, const int* in_sizes, int n_in,
                              void* d_out, int out_size)
{
    (void)in_sizes; (void)n_in; (void)out_size;
    const float* x = (const float*)d_in[0];   // [2,2048,14] float32
    float* out = (float*)d_out;

    cudaFuncSetAttribute(lfq_rows_kernel,
                         cudaFuncAttributeMaxDynamicSharedMemorySize, SMEM_BYTES);
    lfq_rows_kernel<<<GRID_A, NT_A, SMEM_BYTES>>>(x, out);
    lfq_reduce_kernel<<<NBLK_B, 256>>>(out);
}

// round 8
// speedup vs baseline: 1.0252x; 1.0079x over previous
#include <cuda_runtime.h>

// LFQ quantizer, factorized-softmax formulation, v5.
// v4 -> v5: reduce kernel rebuilt for memory-level parallelism.
//   - 128 blocks x 256 threads (full-chip), float4 loads, 8-way rg-split per code quad
//   - fixed-order smem tree + fixed-point atomics => deterministic
//
// probs_j = prod_d sigmoid(400*s_d(j)*x_d) = f(lo 8 bits) * g(hi 6 bits).
// avg_probs = (1/4096) F^T G computed as split-K rank-1 accumulation.

#define RG      74          // row groups
#define RPB     56          // rows per group (last group has 8 valid)
#define GRID_A  (RG * 4)    // 296 blocks = 2 x 148 SMs
#define NT_A    512
#define NCODES  16384
#define NROW    4096
#define NDIM    14
#define NBLK_B  128
#define NT_B    256

// scratch (__device__ globals; no allocations allowed)
__device__ float g_partial[RG * NCODES];           // 4.85 MB split-K partials
__device__ float g_pH[RG];
__device__ float g_pC[RG];
__device__ unsigned long long g_accT;              // fixed-point sum of a*log(a+eps)
__device__ unsigned int g_ticket;

#define FIX_SCALE 1099511627776.0   // 2^40

// dynamic smem layout (floats)
#define OF_F    0                     // f  [RPB][256]
#define OF_SG   (RPB * 256)           // sg [RPB][64]
#define OF_SQ   (OF_SG + RPB * 64)    // sq [RPB][NDIM][2]
#define OF_F03  (OF_SQ + RPB * NDIM * 2)  // f03 [RPB][16]
#define OF_F47  (OF_F03 + RPB * 16)       // f47 [RPB][16]
#define OF_WH   (OF_F47 + RPB * 16)       // swH [16]
#define OF_WC   (OF_WH + 16)              // swC [16]
#define SMEM_FLOATS (OF_WC + 16)
#define SMEM_BYTES  (SMEM_FLOATS * 4)

__global__ __launch_bounds__(NT_A, 2) void lfq_rows_kernel(const float* __restrict__ x,
                                                           float* __restrict__ out)
{
    extern __shared__ __align__(16) float sm[];
    float* F   = sm + OF_F;     // [RPB][256]
    float* SG  = sm + OF_SG;    // [RPB][64]
    float* SQ  = sm + OF_SQ;    // [RPB][NDIM][2]
    float* F03 = sm + OF_F03;   // [RPB][16]
    float* F47 = sm + OF_F47;
    float* SWH = sm + OF_WH;
    float* SWC = sm + OF_WC;

    const int t  = threadIdx.x;
    const int b  = blockIdx.x;
    const int rg = b >> 2;          // row group
    const int h  = b & 3;           // hi quarter
    const int row0  = rg * RPB;
    const int valid = min(RPB, NROW - row0);

    // reset cross-kernel accumulators (visible to kernel B via launch boundary)
    if (b == 0 && t == 0) { g_accT = 0ull; g_ticket = 0u; }

    // ---- phase 0: per-element Bernoulli tables; h==0 also emits outputs/H/C ----
    float hS = 0.f, cS = 0.f;
#pragma unroll
    for (int k = 0; k < 2; k++) {
        const int e = t + NT_A * k;             // covers RPB*NDIM = 784
        if (e < RPB * NDIM) {
            const int row = e / NDIM;
            if (row < valid) {
                const int d = e - row * NDIM;
                const float xv = x[(row0 + row) * NDIM + d];
                const int pos = xv > 0.f ? 1 : 0;
                const float au = fabsf(400.f * xv);
                const float ee = __expf(-au);                  // e^{-|u|}
                const float qmaj = __fdividef(1.f, 1.f + ee);  // sigmoid(|u|)
                const float qmin = ee * qmaj;                  // sigmoid(-|u|)
                SQ[(row * NDIM + d) * 2 + pos]     = qmaj;
                SQ[(row * NDIM + d) * 2 + 1 - pos] = qmin;
                if (h == 0) {
                    hS += log1pf(ee) + qmin * au;              // binary entropy (nats)
                    const float cm = fabsf(xv) - 1.f;
                    cS += cm * cm;
                    out[(row0 + row) * NDIM + d] = pos ? 1.f : -1.f;
                }
            } else {
                const int d = e - row * NDIM;
                SQ[(row * NDIM + d) * 2 + 0] = 0.f;
                SQ[(row * NDIM + d) * 2 + 1] = 0.f;
            }
        }
    }
    if (h == 0) {
        // big-endian packed index, one thread per row
        if (t < valid) {
            int idx = 0;
#pragma unroll
            for (int d = 0; d < NDIM; d++)
                idx |= (x[(row0 + t) * NDIM + d] > 0.f) ? (1 << (13 - d)) : 0;
            out[NROW * NDIM + row0 + t] = (float)idx;
        }
        // warp-level H/C reduce
#pragma unroll
        for (int off = 16; off > 0; off >>= 1) {
            hS += __shfl_down_sync(0xFFFFFFFFu, hS, off);
            cS += __shfl_down_sync(0xFFFFFFFFu, cS, off);
        }
        if ((t & 31) == 0) { SWH[t >> 5] = hS; SWC[t >> 5] = cS; }
    }
    __syncthreads();

    // ---- phase A1: f03 / f47 sub-products ----
#pragma unroll
    for (int k = 0; k < 4; k++) {
        const int e = t + NT_A * k;             // covers [0, 2048) >= 2*RPB*16 = 1792
        if (e < RPB * 16) {
            const int row = e >> 4, i = e & 15;
            const float* q = SQ + row * NDIM * 2;
            F03[e] = q[0 * 2 + (i & 1)] * q[1 * 2 + ((i >> 1) & 1)] *
                     q[2 * 2 + ((i >> 2) & 1)] * q[3 * 2 + ((i >> 3) & 1)];
        } else if (e < 2 * RPB * 16) {
            const int e2 = e - RPB * 16;
            const int row = e2 >> 4, i = e2 & 15;
            const float* q = SQ + row * NDIM * 2;
            F47[e2] = q[4 * 2 + (i & 1)] * q[5 * 2 + ((i >> 1) & 1)] *
                      q[6 * 2 + ((i >> 2) & 1)] * q[7 * 2 + ((i >> 3) & 1)];
        }
    }
    __syncthreads();

    // ---- phase A2: full f table + g table (exact coverage, no guards) ----
#pragma unroll
    for (int k = 0; k < 28; k++) {
        const int e = t + NT_A * k;             // RPB*256 = 14336 = 28*512
        const int row = e >> 8, lo = e & 255;
        F[e] = F03[row * 16 + (lo & 15)] * F47[row * 16 + (lo >> 4)];
    }
#pragma unroll
    for (int k = 0; k < 7; k++) {
        const int e = t + NT_A * k;             // RPB*64 = 3584 = 7*512
        const int row = e >> 6, hc = e & 63;
        const float* q = SQ + row * NDIM * 2;
        SG[e] = q[8 * 2 + (hc & 1)] * q[9 * 2 + ((hc >> 1) & 1)] *
                q[10 * 2 + ((hc >> 2) & 1)] * q[11 * 2 + ((hc >> 3) & 1)] *
                q[12 * 2 + ((hc >> 4) & 1)] * q[13 * 2 + ((hc >> 5) & 1)];
    }
    __syncthreads();

    // ---- phase B: barrier-free rank-1 accumulation (FMA-bound) ----
    const int p   = t & 127;                    // lo pair: lo = 2p, 2p+1
    const int sub = t >> 7;                     // 0..3
    const int hi0 = h * 16 + sub * 4;           // this thread's 4 hi values

    float2 acc[4];
#pragma unroll
    for (int k = 0; k < 4; k++) acc[k] = make_float2(0.f, 0.f);

#pragma unroll 4
    for (int r = 0; r < valid; r++) {
        const float2 fp = *reinterpret_cast<const float2*>(F + r * 256 + 2 * p);  // LDS.64
        const float4 gv = *reinterpret_cast<const float4*>(SG + r * 64 + hi0);    // LDS.128 bcast
        acc[0].x = fmaf(fp.x, gv.x, acc[0].x);  acc[0].y = fmaf(fp.y, gv.x, acc[0].y);
        acc[1].x = fmaf(fp.x, gv.y, acc[1].x);  acc[1].y = fmaf(fp.y, gv.y, acc[1].y);
        acc[2].x = fmaf(fp.x, gv.z, acc[2].x);  acc[2].y = fmaf(fp.y, gv.z, acc[2].y);
        acc[3].x = fmaf(fp.x, gv.w, acc[3].x);  acc[3].y = fmaf(fp.y, gv.w, acc[3].y);
    }

    // store partials: code j = hi*256 + lo
    float2* gp = reinterpret_cast<float2*>(g_partial + rg * NCODES);
#pragma unroll
    for (int k = 0; k < 4; k++)
        gp[((hi0 + k) * 256 + 2 * p) >> 1] = acc[k];

    if (h == 0 && t == 0) {
        float H = 0.f, C = 0.f;
#pragma unroll
        for (int w = 0; w < 16; w++) { H += SWH[w]; C += SWC[w]; }
        g_pH[rg] = H; g_pC[rg] = C;
    }
}

// Reduce: 128 blocks x 256 threads. Thread = (quad, rg-chunk).
//   quad  = blockIdx.x*32 + (t & 31)   -> 4 consecutive codes (float4)
//   chunk = t >> 5                      -> rgs [chunk*10, min(chunk*10+10, 74))
__global__ __launch_bounds__(NT_B) void lfq_reduce_kernel(float* __restrict__ out)
{
    const int t = threadIdx.x;
    const int quad  = blockIdx.x * 32 + (t & 31);
    const int chunk = t >> 5;
    const int rg0 = chunk * 10;

    const float4* gp = reinterpret_cast<const float4*>(g_partial) + quad;

    float4 s = make_float4(0.f, 0.f, 0.f, 0.f);
#pragma unroll
    for (int k = 0; k < 10; k++) {                    // 10 independent predicated loads
        const int rg = rg0 + k;
        if (rg < RG) {
            const float4 v = gp[rg * (NCODES / 4)];   // LDG.128, coalesced per warp
            s.x += v.x; s.y += v.y; s.z += v.z; s.w += v.w;
        }
    }

    __shared__ __align__(16) float4 sred[NT_B];
    __shared__ float fred[NT_B];
    __shared__ int last;
    sred[t] = s;
    __syncthreads();
    // fixed-order tree over the chunk dimension (stride 32 in t)
#pragma unroll
    for (int off = 128; off >= 32; off >>= 1) {
        if (t < off) {
            sred[t].x += sred[t + off].x;  sred[t].y += sred[t + off].y;
            sred[t].z += sred[t + off].z;  sred[t].w += sred[t + off].w;
        }
        __syncthreads();
    }

    // threads 0..31 hold full sums for their quad
    float term = 0.f;
    if (t < 32) {
        const float4 a4 = sred[t];
        const float ax = a4.x * (1.f / (float)NROW);
        const float ay = a4.y * (1.f / (float)NROW);
        const float az = a4.z * (1.f / (float)NROW);
        const float aw = a4.w * (1.f / (float)NROW);
        term = ax * logf(ax + 1e-5f) + ay * logf(ay + 1e-5f) +
               az * logf(az + 1e-5f) + aw * logf(aw + 1e-5f);
#pragma unroll
        for (int off = 16; off > 0; off >>= 1)
            term += __shfl_down_sync(0xFFFFFFFFu, term, off);
        if (t == 0) {
            const long long v = __double2ll_rn((double)term * FIX_SCALE);
            atomicAdd(&g_accT, (unsigned long long)v);
            __threadfence();
            last = (atomicAdd(&g_ticket, 1u) == NBLK_B - 1) ? 1 : 0;
        }
    }
    __syncthreads();
    if (!last) return;

    // final block: assemble scalars
    fred[t] = (t < RG) ? g_pH[t] : 0.f;
    __syncthreads();
#pragma unroll
    for (int off = 128; off > 0; off >>= 1) {
        if (t < off) fred[t] += fred[t + off];
        __syncthreads();
    }
    const float sumH = fred[0];
    __syncthreads();
    fred[t] = (t < RG) ? g_pC[t] : 0.f;
    __syncthreads();
#pragma unroll
    for (int off = 128; off > 0; off >>= 1) {
        if (t < off) fred[t] += fred[t + off];
        __syncthreads();
    }
    const float sumC = fred[0];

    if (t == 0) {
        const long long tot = (long long)atomicAdd(&g_accT, 0ull);
        const float sumT = (float)((double)tot * (1.0 / FIX_SCALE));
        const float per_sample = sumH * (1.f / (float)NROW);
        const float cb_entropy = -sumT;
        float* sc = out + NROW * NDIM + NROW;
        sc[0] = per_sample;
        sc[1] = cb_entropy;
        sc[2] = per_sample - cb_entropy;
        sc[3] = sumC * (1.f / (float)(NROW * NDIM));
    }
}

extern "C" void kernel_launch(void* const* d_in, const int* in_sizes, int n_in,
                              void* d_out, int out_size)
{
    (void)in_sizes; (void)n_in; (void)out_size;
    const float* x = (const float*)d_in[0];   // [2,2048,14] float32
    float* out = (float*)d_out;

    cudaFuncSetAttribute(lfq_rows_kernel,
                         cudaFuncAttributeMaxDynamicSharedMemorySize, SMEM_BYTES);
    lfq_rows_kernel<<<GRID_A, NT_A, SMEM_BYTES>>>(x, out);
    lfq_reduce_kernel<<<NBLK_B, NT_B>>>(out);
}

// round 9
// speedup vs baseline: 1.1282x; 1.1005x over previous
#include <cuda_runtime.h>

// LFQ quantizer, factorized-softmax formulation, v6.
// v5 -> v6: reduce kernel MLP actually realized (explicit load array +
// __launch_bounds__(.,1) so ptxas doesn't serialize the 10 LDG.128s).
//
// probs_j = prod_d sigmoid(400*s_d(j)*x_d) = f(lo 8 bits) * g(hi 6 bits).
// avg_probs = (1/4096) F^T G computed as split-K rank-1 accumulation.

#define RG      74          // row groups
#define RPB     56          // rows per group (last group has 8 valid)
#define GRID_A  (RG * 4)    // 296 blocks = 2 x 148 SMs
#define NT_A    512
#define NCODES  16384
#define NROW    4096
#define NDIM    14
#define NBLK_B  128
#define NT_B    256

// scratch (__device__ globals; no allocations allowed)
__device__ float g_partial[RG * NCODES];           // 4.85 MB split-K partials
__device__ float g_pH[RG];
__device__ float g_pC[RG];
__device__ unsigned long long g_accT;              // fixed-point sum of a*log(a+eps)
__device__ unsigned int g_ticket;

#define FIX_SCALE 1099511627776.0   // 2^40

// dynamic smem layout (floats)
#define OF_F    0                     // f  [RPB][256]
#define OF_SG   (RPB * 256)           // sg [RPB][64]
#define OF_SQ   (OF_SG + RPB * 64)    // sq [RPB][NDIM][2]
#define OF_F03  (OF_SQ + RPB * NDIM * 2)  // f03 [RPB][16]
#define OF_F47  (OF_F03 + RPB * 16)       // f47 [RPB][16]
#define OF_WH   (OF_F47 + RPB * 16)       // swH [16]
#define OF_WC   (OF_WH + 16)              // swC [16]
#define SMEM_FLOATS (OF_WC + 16)
#define SMEM_BYTES  (SMEM_FLOATS * 4)

__global__ __launch_bounds__(NT_A, 2) void lfq_rows_kernel(const float* __restrict__ x,
                                                           float* __restrict__ out)
{
    extern __shared__ __align__(16) float sm[];
    float* F   = sm + OF_F;     // [RPB][256]
    float* SG  = sm + OF_SG;    // [RPB][64]
    float* SQ  = sm + OF_SQ;    // [RPB][NDIM][2]
    float* F03 = sm + OF_F03;   // [RPB][16]
    float* F47 = sm + OF_F47;
    float* SWH = sm + OF_WH;
    float* SWC = sm + OF_WC;

    const int t  = threadIdx.x;
    const int b  = blockIdx.x;
    const int rg = b >> 2;          // row group
    const int h  = b & 3;           // hi quarter
    const int row0  = rg * RPB;
    const int valid = min(RPB, NROW - row0);

    // reset cross-kernel accumulators (visible to kernel B via launch boundary)
    if (b == 0 && t == 0) { g_accT = 0ull; g_ticket = 0u; }

    // ---- phase 0: per-element Bernoulli tables; h==0 also emits outputs/H/C ----
    float hS = 0.f, cS = 0.f;
#pragma unroll
    for (int k = 0; k < 2; k++) {
        const int e = t + NT_A * k;             // covers RPB*NDIM = 784
        if (e < RPB * NDIM) {
            const int row = e / NDIM;
            if (row < valid) {
                const int d = e - row * NDIM;
                const float xv = x[(row0 + row) * NDIM + d];
                const int pos = xv > 0.f ? 1 : 0;
                const float au = fabsf(400.f * xv);
                const float ee = __expf(-au);                  // e^{-|u|}
                const float qmaj = __fdividef(1.f, 1.f + ee);  // sigmoid(|u|)
                const float qmin = ee * qmaj;                  // sigmoid(-|u|)
                SQ[(row * NDIM + d) * 2 + pos]     = qmaj;
                SQ[(row * NDIM + d) * 2 + 1 - pos] = qmin;
                if (h == 0) {
                    hS += log1pf(ee) + qmin * au;              // binary entropy (nats)
                    const float cm = fabsf(xv) - 1.f;
                    cS += cm * cm;
                    out[(row0 + row) * NDIM + d] = pos ? 1.f : -1.f;
                }
            } else {
                const int d = e - row * NDIM;
                SQ[(row * NDIM + d) * 2 + 0] = 0.f;
                SQ[(row * NDIM + d) * 2 + 1] = 0.f;
            }
        }
    }
    if (h == 0) {
        // big-endian packed index, one thread per row
        if (t < valid) {
            int idx = 0;
#pragma unroll
            for (int d = 0; d < NDIM; d++)
                idx |= (x[(row0 + t) * NDIM + d] > 0.f) ? (1 << (13 - d)) : 0;
            out[NROW * NDIM + row0 + t] = (float)idx;
        }
        // warp-level H/C reduce
#pragma unroll
        for (int off = 16; off > 0; off >>= 1) {
            hS += __shfl_down_sync(0xFFFFFFFFu, hS, off);
            cS += __shfl_down_sync(0xFFFFFFFFu, cS, off);
        }
        if ((t & 31) == 0) { SWH[t >> 5] = hS; SWC[t >> 5] = cS; }
    }
    __syncthreads();

    // ---- phase A1: f03 / f47 sub-products ----
#pragma unroll
    for (int k = 0; k < 4; k++) {
        const int e = t + NT_A * k;             // covers [0, 2048) >= 2*RPB*16 = 1792
        if (e < RPB * 16) {
            const int row = e >> 4, i = e & 15;
            const float* q = SQ + row * NDIM * 2;
            F03[e] = q[0 * 2 + (i & 1)] * q[1 * 2 + ((i >> 1) & 1)] *
                     q[2 * 2 + ((i >> 2) & 1)] * q[3 * 2 + ((i >> 3) & 1)];
        } else if (e < 2 * RPB * 16) {
            const int e2 = e - RPB * 16;
            const int row = e2 >> 4, i = e2 & 15;
            const float* q = SQ + row * NDIM * 2;
            F47[e2] = q[4 * 2 + (i & 1)] * q[5 * 2 + ((i >> 1) & 1)] *
                      q[6 * 2 + ((i >> 2) & 1)] * q[7 * 2 + ((i >> 3) & 1)];
        }
    }
    __syncthreads();

    // ---- phase A2: full f table + g table (exact coverage, no guards) ----
#pragma unroll
    for (int k = 0; k < 28; k++) {
        const int e = t + NT_A * k;             // RPB*256 = 14336 = 28*512
        const int row = e >> 8, lo = e & 255;
        F[e] = F03[row * 16 + (lo & 15)] * F47[row * 16 + (lo >> 4)];
    }
#pragma unroll
    for (int k = 0; k < 7; k++) {
        const int e = t + NT_A * k;             // RPB*64 = 3584 = 7*512
        const int row = e >> 6, hc = e & 63;
        const float* q = SQ + row * NDIM * 2;
        SG[e] = q[8 * 2 + (hc & 1)] * q[9 * 2 + ((hc >> 1) & 1)] *
                q[10 * 2 + ((hc >> 2) & 1)] * q[11 * 2 + ((hc >> 3) & 1)] *
                q[12 * 2 + ((hc >> 4) & 1)] * q[13 * 2 + ((hc >> 5) & 1)];
    }
    __syncthreads();

    // ---- phase B: barrier-free rank-1 accumulation (FMA-bound) ----
    const int p   = t & 127;                    // lo pair: lo = 2p, 2p+1
    const int sub = t >> 7;                     // 0..3
    const int hi0 = h * 16 + sub * 4;           // this thread's 4 hi values

    float2 acc[4];
#pragma unroll
    for (int k = 0; k < 4; k++) acc[k] = make_float2(0.f, 0.f);

#pragma unroll 4
    for (int r = 0; r < valid; r++) {
        const float2 fp = *reinterpret_cast<const float2*>(F + r * 256 + 2 * p);  // LDS.64
        const float4 gv = *reinterpret_cast<const float4*>(SG + r * 64 + hi0);    // LDS.128 bcast
        acc[0].x = fmaf(fp.x, gv.x, acc[0].x);  acc[0].y = fmaf(fp.y, gv.x, acc[0].y);
        acc[1].x = fmaf(fp.x, gv.y, acc[1].x);  acc[1].y = fmaf(fp.y, gv.y, acc[1].y);
        acc[2].x = fmaf(fp.x, gv.z, acc[2].x);  acc[2].y = fmaf(fp.y, gv.z, acc[2].y);
        acc[3].x = fmaf(fp.x, gv.w, acc[3].x);  acc[3].y = fmaf(fp.y, gv.w, acc[3].y);
    }

    // store partials: code j = hi*256 + lo
    float2* gp = reinterpret_cast<float2*>(g_partial + rg * NCODES);
#pragma unroll
    for (int k = 0; k < 4; k++)
        gp[((hi0 + k) * 256 + 2 * p) >> 1] = acc[k];

    if (h == 0 && t == 0) {
        float H = 0.f, C = 0.f;
#pragma unroll
        for (int w = 0; w < 16; w++) { H += SWH[w]; C += SWC[w]; }
        g_pH[rg] = H; g_pC[rg] = C;
    }
}

// Reduce: 128 blocks x 256 threads. Thread = (quad, rg-chunk).
//   quad  = blockIdx.x*32 + (t & 31)   -> 4 consecutive codes (float4)
//   chunk = t >> 5                      -> rgs [chunk*10, chunk*10+10) ∩ [0,74)
// v6: loads materialized in an explicit array BEFORE any summation, and
// __launch_bounds__(NT_B, 1) so ptxas keeps all 10 LDG.128 in flight.
__global__ __launch_bounds__(NT_B, 1) void lfq_reduce_kernel(float* __restrict__ out)
{
    const int t = threadIdx.x;
    const int quad  = blockIdx.x * 32 + (t & 31);
    const int chunk = t >> 5;
    const int rg0 = chunk * 10;

    const float4* gp = reinterpret_cast<const float4*>(g_partial) + quad;

    // ---- 10 independent LDG.128, all issued before any use ----
    float4 v[10];
#pragma unroll
    for (int k = 0; k < 10; k++) {
        v[k] = make_float4(0.f, 0.f, 0.f, 0.f);
        if (rg0 + k < RG)
            v[k] = gp[(rg0 + k) * (NCODES / 4)];
    }

    float4 s = make_float4(0.f, 0.f, 0.f, 0.f);
#pragma unroll
    for (int k = 0; k < 10; k++) {
        s.x += v[k].x; s.y += v[k].y; s.z += v[k].z; s.w += v[k].w;
    }

    __shared__ __align__(16) float4 sred[NT_B];
    __shared__ float fred[NT_B];
    __shared__ int last;
    sred[t] = s;
    __syncthreads();
    // fixed-order tree over the chunk dimension (stride 32 in t)
#pragma unroll
    for (int off = 128; off >= 32; off >>= 1) {
        if (t < off) {
            sred[t].x += sred[t + off].x;  sred[t].y += sred[t + off].y;
            sred[t].z += sred[t + off].z;  sred[t].w += sred[t + off].w;
        }
        __syncthreads();
    }

    // threads 0..31 hold full sums for their quad
    float term = 0.f;
    if (t < 32) {
        const float4 a4 = sred[t];
        const float ax = a4.x * (1.f / (float)NROW);
        const float ay = a4.y * (1.f / (float)NROW);
        const float az = a4.z * (1.f / (float)NROW);
        const float aw = a4.w * (1.f / (float)NROW);
        term = ax * logf(ax + 1e-5f) + ay * logf(ay + 1e-5f) +
               az * logf(az + 1e-5f) + aw * logf(aw + 1e-5f);
#pragma unroll
        for (int off = 16; off > 0; off >>= 1)
            term += __shfl_down_sync(0xFFFFFFFFu, term, off);
        if (t == 0) {
            const long long vfx = __double2ll_rn((double)term * FIX_SCALE);
            atomicAdd(&g_accT, (unsigned long long)vfx);
            __threadfence();
            last = (atomicAdd(&g_ticket, 1u) == NBLK_B - 1) ? 1 : 0;
        }
    }
    __syncthreads();
    if (!last) return;

    // final block: assemble scalars
    fred[t] = (t < RG) ? g_pH[t] : 0.f;
    __syncthreads();
#pragma unroll
    for (int off = 128; off > 0; off >>= 1) {
        if (t < off) fred[t] += fred[t + off];
        __syncthreads();
    }
    const float sumH = fred[0];
    __syncthreads();
    fred[t] = (t < RG) ? g_pC[t] : 0.f;
    __syncthreads();
#pragma unroll
    for (int off = 128; off > 0; off >>= 1) {
        if (t < off) fred[t] += fred[t + off];
        __syncthreads();
    }
    const float sumC = fred[0];

    if (t == 0) {
        const long long tot = (long long)atomicAdd(&g_accT, 0ull);
        const float sumT = (float)((double)tot * (1.0 / FIX_SCALE));
        const float per_sample = sumH * (1.f / (float)NROW);
        const float cb_entropy = -sumT;
        float* sc = out + NROW * NDIM + NROW;
        sc[0] = per_sample;
        sc[1] = cb_entropy;
        sc[2] = per_sample - cb_entropy;
        sc[3] = sumC * (1.f / (float)(NROW * NDIM));
    }
}

extern "C" void kernel_launch(void* const* d_in, const int* in_sizes, int n_in,
                              void* d_out, int out_size)
{
    (void)in_sizes; (void)n_in; (void)out_size;
    const float* x = (const float*)d_in[0];   // [2,2048,14] float32
    float* out = (float*)d_out;

    cudaFuncSetAttribute(lfq_rows_kernel,
                         cudaFuncAttributeMaxDynamicSharedMemorySize, SMEM_BYTES);
    lfq_rows_kernel<<<GRID_A, NT_A, SMEM_BYTES>>>(x, out);
    lfq_reduce_kernel<<<NBLK_B, NT_B>>>(out);
}